// round 12
// baseline (speedup 1.0000x reference)
#include <cuda_runtime.h>
#include <cuda_fp16.h>
#include <stdint.h>

#define NMAX 100000
#define EMAX 1600000
#define F    64
#define F4   16
#define GR   64          // gemm rows per block
#define SCAN_B 1024
#define NB1MAX ((NMAX + SCAN_B - 1) / SCAN_B)   // 98
#define NBIN 64          // degree bins for node sort

// ---- scratch (device globals: allocation-free) ----
__device__ int    g_degi[NMAX];
__device__ float  g_dinv[NMAX];
__device__ int    g_off [NMAX + 1];
__device__ int    g_cur [NMAX];
__device__ int    g_bsum[NB1MAX + 1];
__device__ int    g_hist[NBIN];                // degree histogram
__device__ int    g_hcur[NBIN];                // bin cursors (excl-scanned hist)
__device__ int    g_perm[NMAX];                // nodes sorted by degree
__device__ int    g_es  [EMAX];                // dense CSR edge records (src)
__device__ uint4  g_hh  [(size_t)NMAX * 8];    // layer-1 h, fp16 (raw)
__device__ uint4  g_hh2 [(size_t)NMAX * 8];    // layer-2 h, fp16 (pre-scaled)
__device__ float4 g_agg [(size_t)NMAX * F4];   // layer-1 aggregate (fp32)

// ---------------------------------------------------------------------------
__global__ void k_zero(int n) {
    int i = blockIdx.x * blockDim.x + threadIdx.x;
    if (i < n) g_degi[i] = 0;
    if (i < NBIN) g_hist[i] = 0;
}

// Count in-degree; 4 edges/thread via int4 loads of the dst half.
__global__ void k_count(const int* __restrict__ ei, int E) {
    int t = blockIdx.x * blockDim.x + threadIdx.x;
    int e4 = t * 4;
    if (e4 + 3 < E) {
        int4 d = *reinterpret_cast<const int4*>(ei + E + e4);
        atomicAdd(&g_degi[d.x], 1);
        atomicAdd(&g_degi[d.y], 1);
        atomicAdd(&g_degi[d.z], 1);
        atomicAdd(&g_degi[d.w], 1);
    } else {
        for (int e = e4; e < E; e++) atomicAdd(&g_degi[ei[E + e]], 1);
    }
}

// ---- scan stage 1: per-block excl scan; dinv + degree histogram fused ----
__global__ void k_scan_local(int n) {
    __shared__ int wsum[32];
    __shared__ int sh_hist[NBIN];
    int i = blockIdx.x * SCAN_B + threadIdx.x;
    int lane = threadIdx.x & 31, wid = threadIdx.x >> 5;

    if (threadIdx.x < NBIN) sh_hist[threadIdx.x] = 0;
    __syncthreads();

    int v = (i < n) ? g_degi[i] : 0;
    if (i < n) {
        g_dinv[i] = rsqrtf((float)v + 1.0f);   // + self loop
        int bin = v < NBIN - 1 ? v : NBIN - 1;
        atomicAdd(&sh_hist[bin], 1);
    }
    int s = v;
#pragma unroll
    for (int o = 1; o < 32; o <<= 1) {
        int u = __shfl_up_sync(0xffffffffu, s, o);
        if (lane >= o) s += u;
    }
    if (lane == 31) wsum[wid] = s;
    __syncthreads();
    if (wid == 0) {
        int ws = wsum[lane];
#pragma unroll
        for (int o = 1; o < 32; o <<= 1) {
            int u = __shfl_up_sync(0xffffffffu, ws, o);
            if (lane >= o) ws += u;
        }
        wsum[lane] = ws;
    }
    __syncthreads();
    int excl = s - v + (wid > 0 ? wsum[wid - 1] : 0);
    if (i < n) g_off[i] = excl;
    if (threadIdx.x == 0) g_bsum[blockIdx.x] = wsum[31];
    if (threadIdx.x < NBIN && sh_hist[threadIdx.x])
        atomicAdd(&g_hist[threadIdx.x], sh_hist[threadIdx.x]);
}

// ---- scan stage 2 (single block, 128 threads): block sums + hist scan ----
__global__ void k_scan_bsums(int nb) {
    __shared__ int wsum[4];
    __shared__ int h0tot;
    int t = threadIdx.x;
    int lane = t & 31, wid = t >> 5;
    int v = (t < nb) ? g_bsum[t] : 0;
    int s = v;
#pragma unroll
    for (int o = 1; o < 32; o <<= 1) {
        int u = __shfl_up_sync(0xffffffffu, s, o);
        if (lane >= o) s += u;
    }
    if (lane == 31) wsum[wid] = s;
    __syncthreads();
    int base = 0;
    for (int w = 0; w < wid; w++) base += wsum[w];
    if (t < nb) g_bsum[t] = s - v + base;

    // exclusive scan of 64-bin degree histogram -> g_hcur
    int hc = (t < NBIN) ? g_hist[t] : 0;
    int hs = hc;
#pragma unroll
    for (int o = 1; o < 32; o <<= 1) {
        int u = __shfl_up_sync(0xffffffffu, hs, o);
        if (lane >= o) hs += u;
    }
    if (t == 31) h0tot = hs;
    __syncthreads();
    if (t < NBIN) g_hcur[t] = hs - hc + (wid == 1 ? h0tot : 0);
}

// ---- scan stage 3: add block base; scatter node into its degree bin ----
__global__ void k_scan_add(int n, int E) {
    int i = blockIdx.x * SCAN_B + threadIdx.x;
    if (i < n) {
        int o = g_off[i] + g_bsum[blockIdx.x];
        g_off[i] = o;
        g_cur[i] = o;
        int deg = g_degi[i];
        int bin = deg < NBIN - 1 ? deg : NBIN - 1;
        int pos = atomicAdd(&g_hcur[bin], 1);
        g_perm[pos] = i;
    }
    if (i == 0) g_off[n] = E;
}

// Place src into dst bucket; 4 edges/thread via int4 loads.
__global__ void k_place(const int* __restrict__ ei, int E) {
    int t = blockIdx.x * blockDim.x + threadIdx.x;
    int e4 = t * 4;
    if (e4 + 3 < E) {
        int4 sv = *reinterpret_cast<const int4*>(ei + e4);
        int4 dv = *reinterpret_cast<const int4*>(ei + E + e4);
        g_es[atomicAdd(&g_cur[dv.x], 1)] = sv.x;
        g_es[atomicAdd(&g_cur[dv.y], 1)] = sv.y;
        g_es[atomicAdd(&g_cur[dv.z], 1)] = sv.z;
        g_es[atomicAdd(&g_cur[dv.w], 1)] = sv.w;
    } else {
        for (int e = e4; e < E; e++)
            g_es[atomicAdd(&g_cur[ei[E + e]], 1)] = ei[e];
    }
}

// ---------------------------------------------------------------------------
// GEMM: 64 rows/block, 256 threads; thread computes 4 rows x 4 cols.
template <bool L2>
__global__ void k_gemm(const float* in, const float* __restrict__ W,
                       const float* __restrict__ bias, int n)
{
    __shared__ float Ws[F * F];
    __shared__ float xs[GR * F];

    int tid = threadIdx.x;
    int tx = tid & 15;
    int ty = tid >> 4;
    int r0 = blockIdx.x * GR;

    {
        const float4* W4 = reinterpret_cast<const float4*>(W);
        float4* Ws4 = reinterpret_cast<float4*>(Ws);
        for (int i = tid; i < F * F4; i += 256) Ws4[i] = __ldg(&W4[i]);
    }
    {
        float4* xs4 = reinterpret_cast<float4*>(xs);
        for (int i = tid; i < GR * F4; i += 256) {
            int row = i >> 4;
            int c4  = i & 15;
            int gr  = r0 + row;
            float4 v = make_float4(0.f, 0.f, 0.f, 0.f);
            if (L2) {
                if (gr < n) v = g_agg[(size_t)gr * F4 + c4];
                float4 bb = __ldg(&reinterpret_cast<const float4*>(bias)[c4]);
                v.x = fmaxf(v.x + bb.x, 0.f);
                v.y = fmaxf(v.y + bb.y, 0.f);
                v.z = fmaxf(v.z + bb.z, 0.f);
                v.w = fmaxf(v.w + bb.w, 0.f);
            } else {
                if (gr < n)
                    v = __ldg(&reinterpret_cast<const float4*>(in)[(size_t)gr * F4 + c4]);
            }
            xs4[i] = v;
        }
    }
    __syncthreads();

    float4 acc[4];
#pragma unroll
    for (int rr = 0; rr < 4; rr++) acc[rr] = make_float4(0.f, 0.f, 0.f, 0.f);

#pragma unroll
    for (int k = 0; k < F; k++) {
        float4 w = *reinterpret_cast<const float4*>(&Ws[k * F + tx * 4]);
#pragma unroll
        for (int rr = 0; rr < 4; rr++) {
            float xv = xs[(ty + 16 * rr) * F + k];
            acc[rr].x = fmaf(xv, w.x, acc[rr].x);
            acc[rr].y = fmaf(xv, w.y, acc[rr].y);
            acc[rr].z = fmaf(xv, w.z, acc[rr].z);
            acc[rr].w = fmaf(xv, w.w, acc[rr].w);
        }
    }

#pragma unroll
    for (int rr = 0; rr < 4; rr++) {
        int row = r0 + ty + 16 * rr;
        if (row < n) {
            float sc = L2 ? g_dinv[row] : 1.0f;
            __half2 h01 = __floats2half2_rn(acc[rr].x * sc, acc[rr].y * sc);
            __half2 h23 = __floats2half2_rn(acc[rr].z * sc, acc[rr].w * sc);
            uint2 u;
            u.x = reinterpret_cast<unsigned&>(h01);
            u.y = reinterpret_cast<unsigned&>(h23);
            if (L2) reinterpret_cast<uint2*>(g_hh2)[(size_t)row * 16 + tx] = u;
            else    reinterpret_cast<uint2*>(g_hh )[(size_t)row * 16 + tx] = u;
        }
    }
}

// ---------------------------------------------------------------------------
// Aggregate: 8 lanes/node; nodes assigned via degree-sorted g_perm so the 4
// node-groups in each warp have (near-)equal degree -> no divergence waste.
template <bool L2>
__device__ __forceinline__ void agg_edge(const uint4& u, float w, float* acc) {
    float2 f0 = __half22float2(reinterpret_cast<const __half2&>(u.x));
    float2 f1 = __half22float2(reinterpret_cast<const __half2&>(u.y));
    float2 f2 = __half22float2(reinterpret_cast<const __half2&>(u.z));
    float2 f3 = __half22float2(reinterpret_cast<const __half2&>(u.w));
    if (L2) {
        acc[0] += f0.x; acc[1] += f0.y;
        acc[2] += f1.x; acc[3] += f1.y;
        acc[4] += f2.x; acc[5] += f2.y;
        acc[6] += f3.x; acc[7] += f3.y;
    } else {
        acc[0] = fmaf(f0.x, w, acc[0]); acc[1] = fmaf(f0.y, w, acc[1]);
        acc[2] = fmaf(f1.x, w, acc[2]); acc[3] = fmaf(f1.y, w, acc[3]);
        acc[4] = fmaf(f2.x, w, acc[4]); acc[5] = fmaf(f2.y, w, acc[5]);
        acc[6] = fmaf(f3.x, w, acc[6]); acc[7] = fmaf(f3.y, w, acc[7]);
    }
}

template <bool L2>
__global__ void k_aggregate(const float* __restrict__ bias, float* __restrict__ out, int n)
{
    int t = blockIdx.x * blockDim.x + threadIdx.x;
    int gid = t >> 3;
    if (gid >= n) return;
    int node = g_perm[gid];
    int lane = threadIdx.x & 7;
    unsigned gmask = 0xFFu << (threadIdx.x & 24);

    const uint4* H = L2 ? (const uint4*)g_hh2 : (const uint4*)g_hh;

    int beg = g_off[node];
    int end = g_off[node + 1];
    float di = g_dinv[node];

    float acc[8];
    {
        uint4 u = H[(size_t)node * 8 + lane];
        float sw = L2 ? 1.0f : di;
        float2 f0 = __half22float2(reinterpret_cast<__half2&>(u.x));
        float2 f1 = __half22float2(reinterpret_cast<__half2&>(u.y));
        float2 f2 = __half22float2(reinterpret_cast<__half2&>(u.z));
        float2 f3 = __half22float2(reinterpret_cast<__half2&>(u.w));
        acc[0] = f0.x * sw; acc[1] = f0.y * sw;
        acc[2] = f1.x * sw; acc[3] = f1.y * sw;
        acc[4] = f2.x * sw; acc[5] = f2.y * sw;
        acc[6] = f3.x * sw; acc[7] = f3.y * sw;
    }

    int i = beg;
    // ---- fast path: full 8-edge chunks, all 8 gathers in flight ----
    for (; i + 8 <= end; i += 8) {
        int   s_my = __ldg(&g_es[i + lane]);
        float w_my = L2 ? 1.0f : __ldg(&g_dinv[s_my]);

        int sj[8];
#pragma unroll
        for (int j = 0; j < 8; j++) sj[j] = __shfl_sync(gmask, s_my, j, 8);

        uint4 u[8];
#pragma unroll
        for (int j = 0; j < 8; j++) u[j] = __ldg(&H[(size_t)sj[j] * 8 + lane]);

        if (L2) {
#pragma unroll
            for (int j = 0; j < 8; j++) agg_edge<true>(u[j], 1.0f, acc);
        } else {
            float wj[8];
#pragma unroll
            for (int j = 0; j < 8; j++) wj[j] = __shfl_sync(gmask, w_my, j, 8);
#pragma unroll
            for (int j = 0; j < 8; j++) agg_edge<false>(u[j], wj[j], acc);
        }
    }
    // ---- remainder (< 8 edges) ----
    if (i < end) {
        int cnt = end - i;
        int p = i + lane;
        int   s_my = (p < end) ? __ldg(&g_es[p]) : 0;
        float w_my = (!L2 && p < end) ? __ldg(&g_dinv[s_my]) : 1.0f;
        for (int j = 0; j < cnt; j++) {
            int s0 = __shfl_sync(gmask, s_my, j, 8);
            uint4 u = __ldg(&H[(size_t)s0 * 8 + lane]);
            float w0 = L2 ? 1.0f : __shfl_sync(gmask, w_my, j, 8);
            agg_edge<L2>(u, w0, acc);
        }
    }

    size_t oidx = (size_t)node * F4 + lane * 2;
    if (L2) {
        float4 b0 = __ldg(&reinterpret_cast<const float4*>(bias)[lane * 2]);
        float4 b1 = __ldg(&reinterpret_cast<const float4*>(bias)[lane * 2 + 1]);
        float4 o0, o1;
        o0.x = fmaxf(fmaf(acc[0], di, b0.x), 0.f);
        o0.y = fmaxf(fmaf(acc[1], di, b0.y), 0.f);
        o0.z = fmaxf(fmaf(acc[2], di, b0.z), 0.f);
        o0.w = fmaxf(fmaf(acc[3], di, b0.w), 0.f);
        o1.x = fmaxf(fmaf(acc[4], di, b1.x), 0.f);
        o1.y = fmaxf(fmaf(acc[5], di, b1.y), 0.f);
        o1.z = fmaxf(fmaf(acc[6], di, b1.z), 0.f);
        o1.w = fmaxf(fmaf(acc[7], di, b1.w), 0.f);
        reinterpret_cast<float4*>(out)[oidx]     = o0;
        reinterpret_cast<float4*>(out)[oidx + 1] = o1;
    } else {
        g_agg[oidx]     = make_float4(acc[0] * di, acc[1] * di, acc[2] * di, acc[3] * di);
        g_agg[oidx + 1] = make_float4(acc[4] * di, acc[5] * di, acc[6] * di, acc[7] * di);
    }
}

// ---------------------------------------------------------------------------
extern "C" void kernel_launch(void* const* d_in, const int* in_sizes, int n_in,
                              void* d_out, int out_size)
{
    const float* x  = (const float*)d_in[0];
    const int*   ei = (const int*)d_in[1];     // int32 (JAX default x64-off)
    const float* W1 = (const float*)d_in[2];
    const float* b1 = (const float*)d_in[3];
    const float* W2 = (const float*)d_in[4];
    const float* b2 = (const float*)d_in[5];
    float*       out = (float*)d_out;

    int n = in_sizes[0] / F;       // 100000
    int E = in_sizes[1] / 2;       // 1600000
    if (n > NMAX) n = NMAX;
    if (E > EMAX) E = EMAX;

    int nb  = (n + 255) / 256;
    int eb4 = ((E + 3) / 4 + 255) / 256;
    int gb  = (n + GR - 1) / GR;
    int ab  = (n * 8 + 255) / 256;
    int nb1 = (n + SCAN_B - 1) / SCAN_B;

    static cudaStream_t s_side = nullptr;
    static cudaEvent_t  e_fork = nullptr, e_join = nullptr;
    if (!s_side) {
        cudaStreamCreateWithFlags(&s_side, cudaStreamNonBlocking);
        cudaEventCreateWithFlags(&e_fork, cudaEventDisableTiming);
        cudaEventCreateWithFlags(&e_join, cudaEventDisableTiming);
    }

    // ---- fork: layer-1 GEMM on side stream, CSR build on main ----
    cudaEventRecord(e_fork, 0);
    cudaStreamWaitEvent(s_side, e_fork, 0);
    k_gemm<false><<<gb, 256, 0, s_side>>>(x, W1, b1, n);
    cudaEventRecord(e_join, s_side);

    k_zero      <<<nb, 256>>>(n);
    k_count     <<<eb4, 256>>>(ei, E);
    k_scan_local<<<nb1, SCAN_B>>>(n);          // scan + dinv + degree hist
    k_scan_bsums<<<1, 128>>>(nb1);             // block sums + hist scan
    k_scan_add  <<<nb1, SCAN_B>>>(n, E);       // offsets + degree-sort perm
    k_place     <<<eb4, 256>>>(ei, E);

    // ---- join, then layer 1 aggregate / layer 2 ----
    cudaStreamWaitEvent(0, e_join, 0);
    k_aggregate<false><<<ab, 256>>>(b1, out, n);
    k_gemm<true>      <<<gb, 256>>>(x, W2, b1, n);
    k_aggregate<true> <<<ab, 256>>>(b2, out, n);
}

// round 13
// speedup vs baseline: 1.1409x; 1.1409x over previous
#include <cuda_runtime.h>
#include <cuda_fp16.h>
#include <stdint.h>

#define NMAX 100000
#define EMAX 1600000
#define F    64
#define F4   16
#define GR   64          // gemm rows per block
#define AGGN 64          // nodes per fused agg+gemm block
#define SCAN_B 1024
#define NB1MAX ((NMAX + SCAN_B - 1) / SCAN_B)   // 98

// ---- scratch (device globals: allocation-free) ----
// g_degi is self-zeroing: zero at load; k_final resets it after use.
__device__ int    g_degi[NMAX];
__device__ float  g_dinv[NMAX];
__device__ int    g_off [NMAX + 1];
__device__ int    g_cur [NMAX];
__device__ int    g_bsum[NB1MAX + 1];
__device__ int    g_es  [EMAX];                // dense CSR edge records (src)
__device__ uint4  g_hh  [(size_t)NMAX * 8];    // layer-1 h, fp16, prescaled by dinv
__device__ uint4  g_hh2 [(size_t)NMAX * 8];    // layer-2 h, fp16, prescaled by dinv

// ---------------------------------------------------------------------------
// Count in-degree; 4 edges/thread via int4 loads of the dst half.
__global__ void k_count(const int* __restrict__ ei, int E) {
    int t = blockIdx.x * blockDim.x + threadIdx.x;
    int e4 = t * 4;
    if (e4 + 3 < E) {
        int4 d = *reinterpret_cast<const int4*>(ei + E + e4);
        atomicAdd(&g_degi[d.x], 1);
        atomicAdd(&g_degi[d.y], 1);
        atomicAdd(&g_degi[d.z], 1);
        atomicAdd(&g_degi[d.w], 1);
    } else {
        for (int e = e4; e < E; e++) atomicAdd(&g_degi[ei[E + e]], 1);
    }
}

// ---- exclusive scan over degrees (3 stages, dinv fused into stage 1) ----
__global__ void k_scan_local(int n) {
    __shared__ int wsum[32];
    int i = blockIdx.x * SCAN_B + threadIdx.x;
    int lane = threadIdx.x & 31, wid = threadIdx.x >> 5;
    int v = (i < n) ? g_degi[i] : 0;
    if (i < n) g_dinv[i] = rsqrtf((float)v + 1.0f);   // + self loop
    int s = v;
#pragma unroll
    for (int o = 1; o < 32; o <<= 1) {
        int u = __shfl_up_sync(0xffffffffu, s, o);
        if (lane >= o) s += u;
    }
    if (lane == 31) wsum[wid] = s;
    __syncthreads();
    if (wid == 0) {
        int ws = wsum[lane];
#pragma unroll
        for (int o = 1; o < 32; o <<= 1) {
            int u = __shfl_up_sync(0xffffffffu, ws, o);
            if (lane >= o) ws += u;
        }
        wsum[lane] = ws;
    }
    __syncthreads();
    int excl = s - v + (wid > 0 ? wsum[wid - 1] : 0);
    if (i < n) g_off[i] = excl;
    if (threadIdx.x == 0) g_bsum[blockIdx.x] = wsum[31];
}

__global__ void k_scan_bsums(int nb) {   // single block, 128 threads (nb <= 98)
    __shared__ int wsum[4];
    int t = threadIdx.x;
    int lane = t & 31, wid = t >> 5;
    int v = (t < nb) ? g_bsum[t] : 0;
    int s = v;
#pragma unroll
    for (int o = 1; o < 32; o <<= 1) {
        int u = __shfl_up_sync(0xffffffffu, s, o);
        if (lane >= o) s += u;
    }
    if (lane == 31) wsum[wid] = s;
    __syncthreads();
    int base = 0;
    for (int w = 0; w < wid; w++) base += wsum[w];
    if (t < nb) g_bsum[t] = s - v + base;
}

__global__ void k_scan_add(int n, int E) {
    int i = blockIdx.x * SCAN_B + threadIdx.x;
    if (i < n) {
        int o = g_off[i] + g_bsum[blockIdx.x];
        g_off[i] = o;
        g_cur[i] = o;
    }
    if (i == 0) g_off[n] = E;
}

// Place src into dst bucket; 4 edges/thread via int4 loads.
__global__ void k_place(const int* __restrict__ ei, int E) {
    int t = blockIdx.x * blockDim.x + threadIdx.x;
    int e4 = t * 4;
    if (e4 + 3 < E) {
        int4 sv = *reinterpret_cast<const int4*>(ei + e4);
        int4 dv = *reinterpret_cast<const int4*>(ei + E + e4);
        g_es[atomicAdd(&g_cur[dv.x], 1)] = sv.x;
        g_es[atomicAdd(&g_cur[dv.y], 1)] = sv.y;
        g_es[atomicAdd(&g_cur[dv.z], 1)] = sv.z;
        g_es[atomicAdd(&g_cur[dv.w], 1)] = sv.w;
    } else {
        for (int e = e4; e < E; e++)
            g_es[atomicAdd(&g_cur[ei[E + e]], 1)] = ei[e];
    }
}

// ---------------------------------------------------------------------------
// GEMM1: g_hh[r] = (x[r] @ W1) * dinv[r], fp16. 64 rows/block, 256 threads.
// Runs after k_scan_local (dinv ready), overlapped with bsums/add/place.
__global__ void k_gemm1(const float* __restrict__ in, const float* __restrict__ W,
                        int n)
{
    __shared__ float Ws[F * F];
    __shared__ float xs[GR * F];

    int tid = threadIdx.x;
    int tx = tid & 15;
    int ty = tid >> 4;
    int r0 = blockIdx.x * GR;

    {
        const float4* W4 = reinterpret_cast<const float4*>(W);
        float4* Ws4 = reinterpret_cast<float4*>(Ws);
        for (int i = tid; i < F * F4; i += 256) Ws4[i] = __ldg(&W4[i]);
    }
    {
        float4* xs4 = reinterpret_cast<float4*>(xs);
        for (int i = tid; i < GR * F4; i += 256) {
            int row = i >> 4;
            int c4  = i & 15;
            int gr  = r0 + row;
            float4 v = make_float4(0.f, 0.f, 0.f, 0.f);
            if (gr < n)
                v = __ldg(&reinterpret_cast<const float4*>(in)[(size_t)gr * F4 + c4]);
            xs4[i] = v;
        }
    }
    __syncthreads();

    float4 acc[4];
#pragma unroll
    for (int rr = 0; rr < 4; rr++) acc[rr] = make_float4(0.f, 0.f, 0.f, 0.f);

#pragma unroll
    for (int k = 0; k < F; k++) {
        float4 w = *reinterpret_cast<const float4*>(&Ws[k * F + tx * 4]);
#pragma unroll
        for (int rr = 0; rr < 4; rr++) {
            float xv = xs[(ty + 16 * rr) * F + k];
            acc[rr].x = fmaf(xv, w.x, acc[rr].x);
            acc[rr].y = fmaf(xv, w.y, acc[rr].y);
            acc[rr].z = fmaf(xv, w.z, acc[rr].z);
            acc[rr].w = fmaf(xv, w.w, acc[rr].w);
        }
    }

#pragma unroll
    for (int rr = 0; rr < 4; rr++) {
        int row = r0 + ty + 16 * rr;
        if (row < n) {
            float sc = g_dinv[row];
            __half2 h01 = __floats2half2_rn(acc[rr].x * sc, acc[rr].y * sc);
            __half2 h23 = __floats2half2_rn(acc[rr].z * sc, acc[rr].w * sc);
            uint2 u;
            u.x = reinterpret_cast<unsigned&>(h01);
            u.y = reinterpret_cast<unsigned&>(h23);
            reinterpret_cast<uint2*>(g_hh)[(size_t)row * 16 + tx] = u;
        }
    }
}

// ---------------------------------------------------------------------------
// Fused layer-1 aggregate + layer-2 GEMM. 64 nodes/block, 512 threads.
// Phase A: 8 lanes/node gather prescaled g_hh (pure adds), apply dinv+b1+relu,
//          stage 64x64 fp32 tile in smem.
// Phase B: tile @ W2 from smem; write g_hh2 fp16 prescaled by dinv.
__global__ __launch_bounds__(512) void k_agg_gemm(
    const float* __restrict__ W2, const float* __restrict__ b1, int n)
{
    __shared__ float Ws[F * F];      // 16KB
    __shared__ float xs[AGGN * F];   // 16KB

    int tid = threadIdx.x;
    int node0 = blockIdx.x * AGGN;

    // W2 -> smem (independent of aggregation)
    {
        const float4* W4 = reinterpret_cast<const float4*>(W2);
        float4* Ws4 = reinterpret_cast<float4*>(Ws);
        for (int i = tid; i < F * F4; i += 512) Ws4[i] = __ldg(&W4[i]);
    }

    // ---- Phase A: aggregate ----
    int g = tid >> 3;
    int lane = tid & 7;
    int node = node0 + g;
    unsigned gmask = 0xFFu << (tid & 24);

    if (node < n) {
        int beg = g_off[node];
        int end = g_off[node + 1];
        float di = g_dinv[node];

        float acc[8];
        {
            uint4 u = g_hh[(size_t)node * 8 + lane];   // self loop (prescaled)
            float2 f0 = __half22float2(reinterpret_cast<__half2&>(u.x));
            float2 f1 = __half22float2(reinterpret_cast<__half2&>(u.y));
            float2 f2 = __half22float2(reinterpret_cast<__half2&>(u.z));
            float2 f3 = __half22float2(reinterpret_cast<__half2&>(u.w));
            acc[0] = f0.x; acc[1] = f0.y; acc[2] = f1.x; acc[3] = f1.y;
            acc[4] = f2.x; acc[5] = f2.y; acc[6] = f3.x; acc[7] = f3.y;
        }

        int i = beg;
        for (; i + 8 <= end; i += 8) {
            int s_my = __ldg(&g_es[i + lane]);
            int sj[8];
#pragma unroll
            for (int j = 0; j < 8; j++) sj[j] = __shfl_sync(gmask, s_my, j, 8);
            uint4 u[8];
#pragma unroll
            for (int j = 0; j < 8; j++) u[j] = __ldg(&g_hh[(size_t)sj[j] * 8 + lane]);
#pragma unroll
            for (int j = 0; j < 8; j++) {
                float2 f0 = __half22float2(reinterpret_cast<const __half2&>(u[j].x));
                float2 f1 = __half22float2(reinterpret_cast<const __half2&>(u[j].y));
                float2 f2 = __half22float2(reinterpret_cast<const __half2&>(u[j].z));
                float2 f3 = __half22float2(reinterpret_cast<const __half2&>(u[j].w));
                acc[0] += f0.x; acc[1] += f0.y; acc[2] += f1.x; acc[3] += f1.y;
                acc[4] += f2.x; acc[5] += f2.y; acc[6] += f3.x; acc[7] += f3.y;
            }
        }
        if (i < end) {
            int cnt = end - i;
            int p = i + lane;
            int s_my = (p < end) ? __ldg(&g_es[p]) : 0;
            for (int j = 0; j < cnt; j++) {
                int s0 = __shfl_sync(gmask, s_my, j, 8);
                uint4 u = __ldg(&g_hh[(size_t)s0 * 8 + lane]);
                float2 f0 = __half22float2(reinterpret_cast<__half2&>(u.x));
                float2 f1 = __half22float2(reinterpret_cast<__half2&>(u.y));
                float2 f2 = __half22float2(reinterpret_cast<__half2&>(u.z));
                float2 f3 = __half22float2(reinterpret_cast<__half2&>(u.w));
                acc[0] += f0.x; acc[1] += f0.y; acc[2] += f1.x; acc[3] += f1.y;
                acc[4] += f2.x; acc[5] += f2.y; acc[6] += f3.x; acc[7] += f3.y;
            }
        }

        // layer-1 output: relu(acc*dinv + b1) -> smem tile
        float4 bb0 = __ldg(&reinterpret_cast<const float4*>(b1)[lane * 2]);
        float4 bb1 = __ldg(&reinterpret_cast<const float4*>(b1)[lane * 2 + 1]);
        float4 o0, o1;
        o0.x = fmaxf(fmaf(acc[0], di, bb0.x), 0.f);
        o0.y = fmaxf(fmaf(acc[1], di, bb0.y), 0.f);
        o0.z = fmaxf(fmaf(acc[2], di, bb0.z), 0.f);
        o0.w = fmaxf(fmaf(acc[3], di, bb0.w), 0.f);
        o1.x = fmaxf(fmaf(acc[4], di, bb1.x), 0.f);
        o1.y = fmaxf(fmaf(acc[5], di, bb1.y), 0.f);
        o1.z = fmaxf(fmaf(acc[6], di, bb1.z), 0.f);
        o1.w = fmaxf(fmaf(acc[7], di, bb1.w), 0.f);
        *reinterpret_cast<float4*>(&xs[g * F + lane * 8])     = o0;
        *reinterpret_cast<float4*>(&xs[g * F + lane * 8 + 4]) = o1;
    }
    __syncthreads();

    // ---- Phase B: tile @ W2 ----
    int tx = tid & 15;
    int ty = tid >> 4;     // 0..31 -> rows ty, ty+32

    float4 a0 = make_float4(0.f, 0.f, 0.f, 0.f);
    float4 a1 = make_float4(0.f, 0.f, 0.f, 0.f);
#pragma unroll
    for (int k = 0; k < F; k++) {
        float4 w = *reinterpret_cast<const float4*>(&Ws[k * F + tx * 4]);
        float x0 = xs[ty * F + k];
        float x1 = xs[(ty + 32) * F + k];
        a0.x = fmaf(x0, w.x, a0.x); a0.y = fmaf(x0, w.y, a0.y);
        a0.z = fmaf(x0, w.z, a0.z); a0.w = fmaf(x0, w.w, a0.w);
        a1.x = fmaf(x1, w.x, a1.x); a1.y = fmaf(x1, w.y, a1.y);
        a1.z = fmaf(x1, w.z, a1.z); a1.w = fmaf(x1, w.w, a1.w);
    }

    int r0 = node0 + ty;
    int r1 = node0 + ty + 32;
    if (r0 < n) {
        float sc = g_dinv[r0];
        __half2 h01 = __floats2half2_rn(a0.x * sc, a0.y * sc);
        __half2 h23 = __floats2half2_rn(a0.z * sc, a0.w * sc);
        uint2 u;
        u.x = reinterpret_cast<unsigned&>(h01);
        u.y = reinterpret_cast<unsigned&>(h23);
        reinterpret_cast<uint2*>(g_hh2)[(size_t)r0 * 16 + tx] = u;
    }
    if (r1 < n) {
        float sc = g_dinv[r1];
        __half2 h01 = __floats2half2_rn(a1.x * sc, a1.y * sc);
        __half2 h23 = __floats2half2_rn(a1.z * sc, a1.w * sc);
        uint2 u;
        u.x = reinterpret_cast<unsigned&>(h01);
        u.y = reinterpret_cast<unsigned&>(h23);
        reinterpret_cast<uint2*>(g_hh2)[(size_t)r1 * 16 + tx] = u;
    }
}

// ---------------------------------------------------------------------------
// Final aggregate: gather prescaled g_hh2 (pure adds) -> out = relu(acc*di+b2).
// Also resets g_degi (self-zeroing for the next call).
__global__ void k_final(const float* __restrict__ b2, float* __restrict__ out, int n)
{
    int t = blockIdx.x * blockDim.x + threadIdx.x;
    int node = t >> 3;
    if (node >= n) return;
    int lane = threadIdx.x & 7;
    unsigned gmask = 0xFFu << (threadIdx.x & 24);

    if (lane == 0) g_degi[node] = 0;    // self-zero for next call

    int beg = g_off[node];
    int end = g_off[node + 1];
    float di = g_dinv[node];

    float acc[8];
    {
        uint4 u = g_hh2[(size_t)node * 8 + lane];
        float2 f0 = __half22float2(reinterpret_cast<__half2&>(u.x));
        float2 f1 = __half22float2(reinterpret_cast<__half2&>(u.y));
        float2 f2 = __half22float2(reinterpret_cast<__half2&>(u.z));
        float2 f3 = __half22float2(reinterpret_cast<__half2&>(u.w));
        acc[0] = f0.x; acc[1] = f0.y; acc[2] = f1.x; acc[3] = f1.y;
        acc[4] = f2.x; acc[5] = f2.y; acc[6] = f3.x; acc[7] = f3.y;
    }

    int i = beg;
    for (; i + 8 <= end; i += 8) {
        int s_my = __ldg(&g_es[i + lane]);
        int sj[8];
#pragma unroll
        for (int j = 0; j < 8; j++) sj[j] = __shfl_sync(gmask, s_my, j, 8);
        uint4 u[8];
#pragma unroll
        for (int j = 0; j < 8; j++) u[j] = __ldg(&g_hh2[(size_t)sj[j] * 8 + lane]);
#pragma unroll
        for (int j = 0; j < 8; j++) {
            float2 f0 = __half22float2(reinterpret_cast<const __half2&>(u[j].x));
            float2 f1 = __half22float2(reinterpret_cast<const __half2&>(u[j].y));
            float2 f2 = __half22float2(reinterpret_cast<const __half2&>(u[j].z));
            float2 f3 = __half22float2(reinterpret_cast<const __half2&>(u[j].w));
            acc[0] += f0.x; acc[1] += f0.y; acc[2] += f1.x; acc[3] += f1.y;
            acc[4] += f2.x; acc[5] += f2.y; acc[6] += f3.x; acc[7] += f3.y;
        }
    }
    if (i < end) {
        int cnt = end - i;
        int p = i + lane;
        int s_my = (p < end) ? __ldg(&g_es[p]) : 0;
        for (int j = 0; j < cnt; j++) {
            int s0 = __shfl_sync(gmask, s_my, j, 8);
            uint4 u = __ldg(&g_hh2[(size_t)s0 * 8 + lane]);
            float2 f0 = __half22float2(reinterpret_cast<__half2&>(u.x));
            float2 f1 = __half22float2(reinterpret_cast<__half2&>(u.y));
            float2 f2 = __half22float2(reinterpret_cast<__half2&>(u.z));
            float2 f3 = __half22float2(reinterpret_cast<__half2&>(u.w));
            acc[0] += f0.x; acc[1] += f0.y; acc[2] += f1.x; acc[3] += f1.y;
            acc[4] += f2.x; acc[5] += f2.y; acc[6] += f3.x; acc[7] += f3.y;
        }
    }

    float4 bb0 = __ldg(&reinterpret_cast<const float4*>(b2)[lane * 2]);
    float4 bb1 = __ldg(&reinterpret_cast<const float4*>(b2)[lane * 2 + 1]);
    float4 o0, o1;
    o0.x = fmaxf(fmaf(acc[0], di, bb0.x), 0.f);
    o0.y = fmaxf(fmaf(acc[1], di, bb0.y), 0.f);
    o0.z = fmaxf(fmaf(acc[2], di, bb0.z), 0.f);
    o0.w = fmaxf(fmaf(acc[3], di, bb0.w), 0.f);
    o1.x = fmaxf(fmaf(acc[4], di, bb1.x), 0.f);
    o1.y = fmaxf(fmaf(acc[5], di, bb1.y), 0.f);
    o1.z = fmaxf(fmaf(acc[6], di, bb1.z), 0.f);
    o1.w = fmaxf(fmaf(acc[7], di, bb1.w), 0.f);
    size_t oidx = (size_t)node * F4 + lane * 2;
    reinterpret_cast<float4*>(out)[oidx]     = o0;
    reinterpret_cast<float4*>(out)[oidx + 1] = o1;
}

// ---------------------------------------------------------------------------
extern "C" void kernel_launch(void* const* d_in, const int* in_sizes, int n_in,
                              void* d_out, int out_size)
{
    const float* x  = (const float*)d_in[0];
    const int*   ei = (const int*)d_in[1];     // int32 (JAX default x64-off)
    const float* W1 = (const float*)d_in[2];
    const float* b1 = (const float*)d_in[3];
    const float* W2 = (const float*)d_in[4];
    const float* b2 = (const float*)d_in[5];
    float*       out = (float*)d_out;

    int n = in_sizes[0] / F;       // 100000
    int E = in_sizes[1] / 2;       // 1600000
    if (n > NMAX) n = NMAX;
    if (E > EMAX) E = EMAX;

    int eb4 = ((E + 3) / 4 + 255) / 256;
    int gb  = (n + GR - 1) / GR;
    int fb  = (n + AGGN - 1) / AGGN;
    int ab  = (n * 8 + 255) / 256;
    int nb1 = (n + SCAN_B - 1) / SCAN_B;

    static cudaStream_t s_side = nullptr;
    static cudaEvent_t  e_dinv = nullptr, e_join = nullptr;
    if (!s_side) {
        cudaStreamCreateWithFlags(&s_side, cudaStreamNonBlocking);
        cudaEventCreateWithFlags(&e_dinv, cudaEventDisableTiming);
        cudaEventCreateWithFlags(&e_join, cudaEventDisableTiming);
    }

    // ---- CSR build; GEMM1 forks once dinv is ready (after scan_local) ----
    k_count     <<<eb4, 256>>>(ei, E);           // g_degi starts zeroed
    k_scan_local<<<nb1, SCAN_B>>>(n);            // scan stage 1 + dinv
    cudaEventRecord(e_dinv, 0);

    cudaStreamWaitEvent(s_side, e_dinv, 0);
    k_gemm1<<<gb, 256, 0, s_side>>>(x, W1, n);   // overlaps bsums/add/place
    cudaEventRecord(e_join, s_side);

    k_scan_bsums<<<1, 128>>>(nb1);
    k_scan_add  <<<nb1, SCAN_B>>>(n, E);
    k_place     <<<eb4, 256>>>(ei, E);

    // ---- fused layer-1 aggregate + layer-2 GEMM ----
    cudaStreamWaitEvent(0, e_join, 0);
    k_agg_gemm<<<fb, 512>>>(W2, b1, n);

    // ---- final aggregate + epilogue (also resets g_degi) ----
    k_final<<<ab, 256>>>(b2, out, n);
}

// round 14
// speedup vs baseline: 1.1510x; 1.0088x over previous
#include <cuda_runtime.h>
#include <cuda_fp16.h>
#include <stdint.h>

#define NMAX 100000
#define EMAX 1600000
#define F    64
#define F4   16
#define GR   64          // gemm rows per block
#define AGGN 64          // nodes per fused agg+gemm block
#define SCAN_B 1024

// ---- scratch (device globals: allocation-free) ----
// g_degi is self-zeroing: zero at load; k_final resets it after use.
__device__ int    g_degi[NMAX];
__device__ float  g_dinv[NMAX];
__device__ int    g_off [NMAX + 1];
__device__ int    g_cur [NMAX];
__device__ int    g_es  [EMAX];                // dense CSR edge records (src)
__device__ uint4  g_hh  [(size_t)NMAX * 8];    // layer-1 h, fp16, prescaled by dinv
__device__ uint4  g_hh2 [(size_t)NMAX * 8];    // layer-2 h, fp16, prescaled by dinv

// ---------------------------------------------------------------------------
// Count in-degree; 4 edges/thread via int4 loads of the dst half.
__global__ void k_count(const int* __restrict__ ei, int E) {
    int t = blockIdx.x * blockDim.x + threadIdx.x;
    int e4 = t * 4;
    if (e4 + 3 < E) {
        int4 d = *reinterpret_cast<const int4*>(ei + E + e4);
        atomicAdd(&g_degi[d.x], 1);
        atomicAdd(&g_degi[d.y], 1);
        atomicAdd(&g_degi[d.z], 1);
        atomicAdd(&g_degi[d.w], 1);
    } else {
        for (int e = e4; e < E; e++) atomicAdd(&g_degi[ei[E + e]], 1);
    }
}

// ---------------------------------------------------------------------------
// Single-kernel exclusive scan: each block redundantly reduces the degree
// prefix [0, blockStart) for its base (L2-hot, ~50KB avg — no cross-block
// communication), then local-scans its 1024 elements. Also computes dinv
// and seeds g_cur. One launch replaces the old 3-stage scan chain.
__global__ void k_scan(int n, int E) {
    __shared__ int wsum[32];
    __shared__ int sbase;
    int b = blockIdx.x;
    int tid = threadIdx.x;
    int lane = tid & 31, wid = tid >> 5;
    int start = b * SCAN_B;

    // 1) base = sum(g_degi[0..start))
    int ps = 0;
    for (int i = tid; i < start; i += SCAN_B) ps += g_degi[i];
#pragma unroll
    for (int o = 16; o; o >>= 1) ps += __shfl_down_sync(0xffffffffu, ps, o);
    if (lane == 0) wsum[wid] = ps;
    __syncthreads();
    if (tid == 0) {
        int s = 0;
#pragma unroll
        for (int w = 0; w < 32; w++) s += wsum[w];
        sbase = s;
    }
    __syncthreads();               // tid0 done reading wsum; safe to reuse below
    int base = sbase;

    // 2) local exclusive scan of this block's 1024 degrees
    int i = start + tid;
    int v = (i < n) ? g_degi[i] : 0;
    if (i < n) g_dinv[i] = rsqrtf((float)v + 1.0f);   // + self loop
    int s = v;
#pragma unroll
    for (int o = 1; o < 32; o <<= 1) {
        int u = __shfl_up_sync(0xffffffffu, s, o);
        if (lane >= o) s += u;
    }
    if (lane == 31) wsum[wid] = s;
    __syncthreads();
    if (wid == 0) {
        int ws = wsum[lane];
#pragma unroll
        for (int o = 1; o < 32; o <<= 1) {
            int u = __shfl_up_sync(0xffffffffu, ws, o);
            if (lane >= o) ws += u;
        }
        wsum[lane] = ws;
    }
    __syncthreads();
    int excl = s - v + (wid > 0 ? wsum[wid - 1] : 0) + base;
    if (i < n) {
        g_off[i] = excl;
        g_cur[i] = excl;
    }
    if (i == 0) g_off[n] = E;
}

// Place src into dst bucket; 4 edges/thread via int4 loads.
__global__ void k_place(const int* __restrict__ ei, int E) {
    int t = blockIdx.x * blockDim.x + threadIdx.x;
    int e4 = t * 4;
    if (e4 + 3 < E) {
        int4 sv = *reinterpret_cast<const int4*>(ei + e4);
        int4 dv = *reinterpret_cast<const int4*>(ei + E + e4);
        g_es[atomicAdd(&g_cur[dv.x], 1)] = sv.x;
        g_es[atomicAdd(&g_cur[dv.y], 1)] = sv.y;
        g_es[atomicAdd(&g_cur[dv.z], 1)] = sv.z;
        g_es[atomicAdd(&g_cur[dv.w], 1)] = sv.w;
    } else {
        for (int e = e4; e < E; e++)
            g_es[atomicAdd(&g_cur[ei[E + e]], 1)] = ei[e];
    }
}

// ---------------------------------------------------------------------------
// GEMM1: g_hh[r] = (x[r] @ W1) * dinv[r], fp16. 64 rows/block, 256 threads.
// Forks after k_scan (dinv ready); overlaps k_place.
__global__ void k_gemm1(const float* __restrict__ in, const float* __restrict__ W,
                        int n)
{
    __shared__ float Ws[F * F];
    __shared__ float xs[GR * F];

    int tid = threadIdx.x;
    int tx = tid & 15;
    int ty = tid >> 4;
    int r0 = blockIdx.x * GR;

    {
        const float4* W4 = reinterpret_cast<const float4*>(W);
        float4* Ws4 = reinterpret_cast<float4*>(Ws);
        for (int i = tid; i < F * F4; i += 256) Ws4[i] = __ldg(&W4[i]);
    }
    {
        float4* xs4 = reinterpret_cast<float4*>(xs);
        for (int i = tid; i < GR * F4; i += 256) {
            int row = i >> 4;
            int c4  = i & 15;
            int gr  = r0 + row;
            float4 v = make_float4(0.f, 0.f, 0.f, 0.f);
            if (gr < n)
                v = __ldg(&reinterpret_cast<const float4*>(in)[(size_t)gr * F4 + c4]);
            xs4[i] = v;
        }
    }
    __syncthreads();

    float4 acc[4];
#pragma unroll
    for (int rr = 0; rr < 4; rr++) acc[rr] = make_float4(0.f, 0.f, 0.f, 0.f);

#pragma unroll
    for (int k = 0; k < F; k++) {
        float4 w = *reinterpret_cast<const float4*>(&Ws[k * F + tx * 4]);
#pragma unroll
        for (int rr = 0; rr < 4; rr++) {
            float xv = xs[(ty + 16 * rr) * F + k];
            acc[rr].x = fmaf(xv, w.x, acc[rr].x);
            acc[rr].y = fmaf(xv, w.y, acc[rr].y);
            acc[rr].z = fmaf(xv, w.z, acc[rr].z);
            acc[rr].w = fmaf(xv, w.w, acc[rr].w);
        }
    }

#pragma unroll
    for (int rr = 0; rr < 4; rr++) {
        int row = r0 + ty + 16 * rr;
        if (row < n) {
            float sc = g_dinv[row];
            __half2 h01 = __floats2half2_rn(acc[rr].x * sc, acc[rr].y * sc);
            __half2 h23 = __floats2half2_rn(acc[rr].z * sc, acc[rr].w * sc);
            uint2 u;
            u.x = reinterpret_cast<unsigned&>(h01);
            u.y = reinterpret_cast<unsigned&>(h23);
            reinterpret_cast<uint2*>(g_hh)[(size_t)row * 16 + tx] = u;
        }
    }
}

// ---------------------------------------------------------------------------
// Fused layer-1 aggregate + layer-2 GEMM. 64 nodes/block, 512 threads.
__global__ __launch_bounds__(512) void k_agg_gemm(
    const float* __restrict__ W2, const float* __restrict__ b1, int n)
{
    __shared__ float Ws[F * F];      // 16KB
    __shared__ float xs[AGGN * F];   // 16KB

    int tid = threadIdx.x;
    int node0 = blockIdx.x * AGGN;

    {
        const float4* W4 = reinterpret_cast<const float4*>(W2);
        float4* Ws4 = reinterpret_cast<float4*>(Ws);
        for (int i = tid; i < F * F4; i += 512) Ws4[i] = __ldg(&W4[i]);
    }

    // ---- Phase A: aggregate (prescaled g_hh, pure adds) ----
    int g = tid >> 3;
    int lane = tid & 7;
    int node = node0 + g;
    unsigned gmask = 0xFFu << (tid & 24);

    if (node < n) {
        int beg = g_off[node];
        int end = g_off[node + 1];
        float di = g_dinv[node];

        float acc[8];
        {
            uint4 u = g_hh[(size_t)node * 8 + lane];   // self loop (prescaled)
            float2 f0 = __half22float2(reinterpret_cast<__half2&>(u.x));
            float2 f1 = __half22float2(reinterpret_cast<__half2&>(u.y));
            float2 f2 = __half22float2(reinterpret_cast<__half2&>(u.z));
            float2 f3 = __half22float2(reinterpret_cast<__half2&>(u.w));
            acc[0] = f0.x; acc[1] = f0.y; acc[2] = f1.x; acc[3] = f1.y;
            acc[4] = f2.x; acc[5] = f2.y; acc[6] = f3.x; acc[7] = f3.y;
        }

        int i = beg;
        for (; i + 8 <= end; i += 8) {
            int s_my = __ldg(&g_es[i + lane]);
            int sj[8];
#pragma unroll
            for (int j = 0; j < 8; j++) sj[j] = __shfl_sync(gmask, s_my, j, 8);
            uint4 u[8];
#pragma unroll
            for (int j = 0; j < 8; j++) u[j] = __ldg(&g_hh[(size_t)sj[j] * 8 + lane]);
#pragma unroll
            for (int j = 0; j < 8; j++) {
                float2 f0 = __half22float2(reinterpret_cast<const __half2&>(u[j].x));
                float2 f1 = __half22float2(reinterpret_cast<const __half2&>(u[j].y));
                float2 f2 = __half22float2(reinterpret_cast<const __half2&>(u[j].z));
                float2 f3 = __half22float2(reinterpret_cast<const __half2&>(u[j].w));
                acc[0] += f0.x; acc[1] += f0.y; acc[2] += f1.x; acc[3] += f1.y;
                acc[4] += f2.x; acc[5] += f2.y; acc[6] += f3.x; acc[7] += f3.y;
            }
        }
        if (i < end) {
            int cnt = end - i;
            int p = i + lane;
            int s_my = (p < end) ? __ldg(&g_es[p]) : 0;
            for (int j = 0; j < cnt; j++) {
                int s0 = __shfl_sync(gmask, s_my, j, 8);
                uint4 u = __ldg(&g_hh[(size_t)s0 * 8 + lane]);
                float2 f0 = __half22float2(reinterpret_cast<__half2&>(u.x));
                float2 f1 = __half22float2(reinterpret_cast<__half2&>(u.y));
                float2 f2 = __half22float2(reinterpret_cast<__half2&>(u.z));
                float2 f3 = __half22float2(reinterpret_cast<__half2&>(u.w));
                acc[0] += f0.x; acc[1] += f0.y; acc[2] += f1.x; acc[3] += f1.y;
                acc[4] += f2.x; acc[5] += f2.y; acc[6] += f3.x; acc[7] += f3.y;
            }
        }

        float4 bb0 = __ldg(&reinterpret_cast<const float4*>(b1)[lane * 2]);
        float4 bb1 = __ldg(&reinterpret_cast<const float4*>(b1)[lane * 2 + 1]);
        float4 o0, o1;
        o0.x = fmaxf(fmaf(acc[0], di, bb0.x), 0.f);
        o0.y = fmaxf(fmaf(acc[1], di, bb0.y), 0.f);
        o0.z = fmaxf(fmaf(acc[2], di, bb0.z), 0.f);
        o0.w = fmaxf(fmaf(acc[3], di, bb0.w), 0.f);
        o1.x = fmaxf(fmaf(acc[4], di, bb1.x), 0.f);
        o1.y = fmaxf(fmaf(acc[5], di, bb1.y), 0.f);
        o1.z = fmaxf(fmaf(acc[6], di, bb1.z), 0.f);
        o1.w = fmaxf(fmaf(acc[7], di, bb1.w), 0.f);
        *reinterpret_cast<float4*>(&xs[g * F + lane * 8])     = o0;
        *reinterpret_cast<float4*>(&xs[g * F + lane * 8 + 4]) = o1;
    }
    __syncthreads();

    // ---- Phase B: tile @ W2 ----
    int tx = tid & 15;
    int ty = tid >> 4;     // 0..31 -> rows ty, ty+32

    float4 a0 = make_float4(0.f, 0.f, 0.f, 0.f);
    float4 a1 = make_float4(0.f, 0.f, 0.f, 0.f);
#pragma unroll
    for (int k = 0; k < F; k++) {
        float4 w = *reinterpret_cast<const float4*>(&Ws[k * F + tx * 4]);
        float x0 = xs[ty * F + k];
        float x1 = xs[(ty + 32) * F + k];
        a0.x = fmaf(x0, w.x, a0.x); a0.y = fmaf(x0, w.y, a0.y);
        a0.z = fmaf(x0, w.z, a0.z); a0.w = fmaf(x0, w.w, a0.w);
        a1.x = fmaf(x1, w.x, a1.x); a1.y = fmaf(x1, w.y, a1.y);
        a1.z = fmaf(x1, w.z, a1.z); a1.w = fmaf(x1, w.w, a1.w);
    }

    int r0 = node0 + ty;
    int r1 = node0 + ty + 32;
    if (r0 < n) {
        float sc = g_dinv[r0];
        __half2 h01 = __floats2half2_rn(a0.x * sc, a0.y * sc);
        __half2 h23 = __floats2half2_rn(a0.z * sc, a0.w * sc);
        uint2 u;
        u.x = reinterpret_cast<unsigned&>(h01);
        u.y = reinterpret_cast<unsigned&>(h23);
        reinterpret_cast<uint2*>(g_hh2)[(size_t)r0 * 16 + tx] = u;
    }
    if (r1 < n) {
        float sc = g_dinv[r1];
        __half2 h01 = __floats2half2_rn(a1.x * sc, a1.y * sc);
        __half2 h23 = __floats2half2_rn(a1.z * sc, a1.w * sc);
        uint2 u;
        u.x = reinterpret_cast<unsigned&>(h01);
        u.y = reinterpret_cast<unsigned&>(h23);
        reinterpret_cast<uint2*>(g_hh2)[(size_t)r1 * 16 + tx] = u;
    }
}

// ---------------------------------------------------------------------------
// Final aggregate: gather prescaled g_hh2 -> out = relu(acc*di + b2).
// Also resets g_degi (self-zeroing for the next call).
__global__ void k_final(const float* __restrict__ b2, float* __restrict__ out, int n)
{
    int t = blockIdx.x * blockDim.x + threadIdx.x;
    int node = t >> 3;
    if (node >= n) return;
    int lane = threadIdx.x & 7;
    unsigned gmask = 0xFFu << (threadIdx.x & 24);

    if (lane == 0) g_degi[node] = 0;    // self-zero for next call

    int beg = g_off[node];
    int end = g_off[node + 1];
    float di = g_dinv[node];

    float acc[8];
    {
        uint4 u = g_hh2[(size_t)node * 8 + lane];
        float2 f0 = __half22float2(reinterpret_cast<__half2&>(u.x));
        float2 f1 = __half22float2(reinterpret_cast<__half2&>(u.y));
        float2 f2 = __half22float2(reinterpret_cast<__half2&>(u.z));
        float2 f3 = __half22float2(reinterpret_cast<__half2&>(u.w));
        acc[0] = f0.x; acc[1] = f0.y; acc[2] = f1.x; acc[3] = f1.y;
        acc[4] = f2.x; acc[5] = f2.y; acc[6] = f3.x; acc[7] = f3.y;
    }

    int i = beg;
    for (; i + 8 <= end; i += 8) {
        int s_my = __ldg(&g_es[i + lane]);
        int sj[8];
#pragma unroll
        for (int j = 0; j < 8; j++) sj[j] = __shfl_sync(gmask, s_my, j, 8);
        uint4 u[8];
#pragma unroll
        for (int j = 0; j < 8; j++) u[j] = __ldg(&g_hh2[(size_t)sj[j] * 8 + lane]);
#pragma unroll
        for (int j = 0; j < 8; j++) {
            float2 f0 = __half22float2(reinterpret_cast<const __half2&>(u[j].x));
            float2 f1 = __half22float2(reinterpret_cast<const __half2&>(u[j].y));
            float2 f2 = __half22float2(reinterpret_cast<const __half2&>(u[j].z));
            float2 f3 = __half22float2(reinterpret_cast<const __half2&>(u[j].w));
            acc[0] += f0.x; acc[1] += f0.y; acc[2] += f1.x; acc[3] += f1.y;
            acc[4] += f2.x; acc[5] += f2.y; acc[6] += f3.x; acc[7] += f3.y;
        }
    }
    if (i < end) {
        int cnt = end - i;
        int p = i + lane;
        int s_my = (p < end) ? __ldg(&g_es[p]) : 0;
        for (int j = 0; j < cnt; j++) {
            int s0 = __shfl_sync(gmask, s_my, j, 8);
            uint4 u = __ldg(&g_hh2[(size_t)s0 * 8 + lane]);
            float2 f0 = __half22float2(reinterpret_cast<__half2&>(u.x));
            float2 f1 = __half22float2(reinterpret_cast<__half2&>(u.y));
            float2 f2 = __half22float2(reinterpret_cast<__half2&>(u.z));
            float2 f3 = __half22float2(reinterpret_cast<__half2&>(u.w));
            acc[0] += f0.x; acc[1] += f0.y; acc[2] += f1.x; acc[3] += f1.y;
            acc[4] += f2.x; acc[5] += f2.y; acc[6] += f3.x; acc[7] += f3.y;
        }
    }

    float4 bb0 = __ldg(&reinterpret_cast<const float4*>(b2)[lane * 2]);
    float4 bb1 = __ldg(&reinterpret_cast<const float4*>(b2)[lane * 2 + 1]);
    float4 o0, o1;
    o0.x = fmaxf(fmaf(acc[0], di, bb0.x), 0.f);
    o0.y = fmaxf(fmaf(acc[1], di, bb0.y), 0.f);
    o0.z = fmaxf(fmaf(acc[2], di, bb0.z), 0.f);
    o0.w = fmaxf(fmaf(acc[3], di, bb0.w), 0.f);
    o1.x = fmaxf(fmaf(acc[4], di, bb1.x), 0.f);
    o1.y = fmaxf(fmaf(acc[5], di, bb1.y), 0.f);
    o1.z = fmaxf(fmaf(acc[6], di, bb1.z), 0.f);
    o1.w = fmaxf(fmaf(acc[7], di, bb1.w), 0.f);
    size_t oidx = (size_t)node * F4 + lane * 2;
    reinterpret_cast<float4*>(out)[oidx]     = o0;
    reinterpret_cast<float4*>(out)[oidx + 1] = o1;
}

// ---------------------------------------------------------------------------
extern "C" void kernel_launch(void* const* d_in, const int* in_sizes, int n_in,
                              void* d_out, int out_size)
{
    const float* x  = (const float*)d_in[0];
    const int*   ei = (const int*)d_in[1];     // int32 (JAX default x64-off)
    const float* W1 = (const float*)d_in[2];
    const float* b1 = (const float*)d_in[3];
    const float* W2 = (const float*)d_in[4];
    const float* b2 = (const float*)d_in[5];
    float*       out = (float*)d_out;

    int n = in_sizes[0] / F;       // 100000
    int E = in_sizes[1] / 2;       // 1600000
    if (n > NMAX) n = NMAX;
    if (E > EMAX) E = EMAX;

    int eb4 = ((E + 3) / 4 + 255) / 256;
    int gb  = (n + GR - 1) / GR;
    int fb  = (n + AGGN - 1) / AGGN;
    int ab  = (n * 8 + 255) / 256;
    int nb1 = (n + SCAN_B - 1) / SCAN_B;

    static cudaStream_t s_side = nullptr;
    static cudaEvent_t  e_dinv = nullptr, e_join = nullptr;
    if (!s_side) {
        cudaStreamCreateWithFlags(&s_side, cudaStreamNonBlocking);
        cudaEventCreateWithFlags(&e_dinv, cudaEventDisableTiming);
        cudaEventCreateWithFlags(&e_join, cudaEventDisableTiming);
    }

    // ---- CSR build: count -> single-kernel scan -> place ----
    k_count<<<eb4, 256>>>(ei, E);              // g_degi starts zeroed
    k_scan <<<nb1, SCAN_B>>>(n, E);            // scan + dinv + cur, one launch
    cudaEventRecord(e_dinv, 0);

    cudaStreamWaitEvent(s_side, e_dinv, 0);
    k_gemm1<<<gb, 256, 0, s_side>>>(x, W1, n); // overlaps k_place
    cudaEventRecord(e_join, s_side);

    k_place<<<eb4, 256>>>(ei, E);

    // ---- fused layer-1 aggregate + layer-2 GEMM ----
    cudaStreamWaitEvent(0, e_join, 0);
    k_agg_gemm<<<fb, 512>>>(W2, b1, n);

    // ---- final aggregate + epilogue (also resets g_degi) ----
    k_final<<<ab, 256>>>(b2, out, n);
}